// round 1
// baseline (speedup 1.0000x reference)
#include <cuda_runtime.h>

#define BIN 256
#define IM 256
#define NPIX (IM * IM)          // 65536
#define NHIST 4                 // {inp,ref} x {b0,b1}

// Scratch: 4 histograms of 256x256 float = 1 MB (device global; no allocs).
__device__ float g_hist[NHIST * BIN * BIN];

// ---------------------------------------------------------------------------
// Kernel 1: zero the histograms (float4 stores, 64K threads)
// ---------------------------------------------------------------------------
__global__ void zero_hist_kernel() {
    int i = blockIdx.x * blockDim.x + threadIdx.x;
    if (i < NHIST * BIN * BIN / 4) {
        reinterpret_cast<float4*>(g_hist)[i] = make_float4(0.f, 0.f, 0.f, 0.f);
    }
}

// Triangular-kernel weight, numerics matching the reference exactly:
//   bias_k = 1 - 2k/256 (exact dyadic), a1 = u + bias_k, w = relu(1 - |a1|*255)
__device__ __forceinline__ float tri_w(float u, int k) {
    float a1 = u + (1.0f - (float)k * 0.0078125f);
    return fmaxf(0.0f, 1.0f - fabsf(a1) * 255.0f);
}

// ---------------------------------------------------------------------------
// Kernel 2: per-pixel scatter of the (at most) 2x2 outer-product patch.
// hist2d[b,j,r] = sum_hw hb_j(ch1) * ha_r(ch0)   (mean applied later)
// Each thread handles one (b, pixel) for BOTH input tensors.
// ---------------------------------------------------------------------------
__global__ void scatter_kernel(const float* __restrict__ inp,
                               const float* __restrict__ ref) {
    int idx = blockIdx.x * blockDim.x + threadIdx.x;
    if (idx >= 2 * NPIX) return;
    int b = idx >> 16;          // batch
    int p = idx & (NPIX - 1);   // pixel

#pragma unroll
    for (int t = 0; t < 2; ++t) {
        const float* img = (t == 0) ? inp : ref;
        float xa = img[(b * 2 + 0) * NPIX + p];   // channel 0 -> r axis
        float xb = img[(b * 2 + 1) * NPIX + p];   // channel 1 -> j axis
        float ua = (xa + 1.0f) * 0.5f;
        float ub = (xb + 1.0f) * 0.5f;

        // support of the triangular kernel covers bins {floor(t), floor(t)+1}
        int ka = (int)floorf(ua * 128.0f + 128.0f);
        int kb = (int)floorf(ub * 128.0f + 128.0f);

        int   kas[2] = {ka, ka + 1};
        int   kbs[2] = {kb, kb + 1};
        float was[2] = {tri_w(ua, ka), tri_w(ua, ka + 1)};
        float wbs[2] = {tri_w(ub, kb), tri_w(ub, kb + 1)};

        float* H = g_hist + (t * 2 + b) * BIN * BIN;
#pragma unroll
        for (int jj = 0; jj < 2; ++jj) {
            if (wbs[jj] <= 0.0f || (unsigned)kbs[jj] >= BIN) continue;
#pragma unroll
            for (int rr = 0; rr < 2; ++rr) {
                if (was[rr] <= 0.0f || (unsigned)kas[rr] >= BIN) continue;
                atomicAdd(H + kbs[jj] * BIN + kas[rr], wbs[jj] * was[rr]);
            }
        }
    }
}

// ---------------------------------------------------------------------------
// Kernel 3: Huber loss between the two (mean-normalized) histograms.
// out[b,0,j,r], 2*65536 elements.
// ---------------------------------------------------------------------------
__global__ void loss_kernel(float* __restrict__ out) {
    int i = blockIdx.x * blockDim.x + threadIdx.x;
    if (i >= 2 * BIN * BIN) return;
    int b  = i >> 16;
    int jr = i & (BIN * BIN - 1);

    const float inv = 1.0f / (float)NPIX;
    float hi = g_hist[(0 * 2 + b) * BIN * BIN + jr] * inv;
    float hg = g_hist[(1 * 2 + b) * BIN * BIN + jr] * inv;

    float mann = fabsf(hi - hg);
    float loss = (mann < 0.01f) ? (0.5f * mann * mann) * 100.0f
                                : (mann - 0.005f);
    out[i] = loss;
}

// ---------------------------------------------------------------------------
extern "C" void kernel_launch(void* const* d_in, const int* in_sizes, int n_in,
                              void* d_out, int out_size) {
    const float* inp = (const float*)d_in[0];
    const float* ref = (const float*)d_in[1];
    float* out = (float*)d_out;

    zero_hist_kernel<<<(NHIST * BIN * BIN / 4 + 255) / 256, 256>>>();
    scatter_kernel<<<(2 * NPIX + 255) / 256, 256>>>(inp, ref);
    loss_kernel<<<(2 * BIN * BIN + 255) / 256, 256>>>(out);
}